// round 1
// baseline (speedup 1.0000x reference)
#include <cuda_runtime.h>
#include <math.h>

// ---------------------------------------------------------------------------
// Attention_49185965473896: single-head causal attention + interleaved RoPE
//   B=4, T=2048, C=1024 (fp32)
//   Q = rope(x@Wq+bq); K = rope(x@Wk+bk); V = x@Wv+bv
//   S = QK^T/sqrt(C), causal mask, softmax -> P
//   out = (P@V)@Wo + bo
// Round 1: fp32 tiled SGEMM baseline with causal work-skipping.
// ---------------------------------------------------------------------------

#define BM 64
#define BN 64
#define BK 16
#define NTHREADS 256

static const int kB = 4;
static const int kT = 2048;
static const int kC = 1024;

// Scratch (static device arrays; allocation is forbidden)
__device__ float g_Q[(size_t)4 * 2048 * 1024];
__device__ float g_K[(size_t)4 * 2048 * 1024];
__device__ float g_V[(size_t)4 * 2048 * 1024];
__device__ float g_O[(size_t)4 * 2048 * 1024];
__device__ float g_S[(size_t)4 * 2048 * 2048];

// ---------------------------------------------------------------------------
// Generic Y = X@W (+bias), row-major, M%64==0, N%64==0, K%16==0.
// causal_k != 0: truncate K-loop at (blockIdx.y+1)*BM (used for P@V).
// ---------------------------------------------------------------------------
__global__ __launch_bounds__(NTHREADS) void gemm_kernel(
    const float* __restrict__ X, const float* __restrict__ W,
    const float* __restrict__ bias, float* __restrict__ Y,
    int M, int N, int K, int causal_k)
{
    __shared__ float As[BM][BK];
    __shared__ float Bs[BK][BN];

    const int tid = threadIdx.x;
    const int tx = tid & 15;        // 0..15 -> N micro
    const int ty = tid >> 4;        // 0..15 -> M micro
    const int m0 = blockIdx.y * BM;
    const int n0 = blockIdx.x * BN;

    const int arow = tid >> 2;          // 0..63
    const int acol = (tid & 3) * 4;     // 0,4,8,12
    const int brow = tid >> 4;          // 0..15
    const int bcol = (tid & 15) * 4;    // 0..60

    int Kend = causal_k ? min(K, (int)(blockIdx.y + 1) * BM) : K;

    float acc[4][4];
    #pragma unroll
    for (int r = 0; r < 4; r++)
        #pragma unroll
        for (int c = 0; c < 4; c++) acc[r][c] = 0.0f;

    for (int k0 = 0; k0 < Kend; k0 += BK) {
        *reinterpret_cast<float4*>(&As[arow][acol]) =
            *reinterpret_cast<const float4*>(&X[(size_t)(m0 + arow) * K + k0 + acol]);
        *reinterpret_cast<float4*>(&Bs[brow][bcol]) =
            *reinterpret_cast<const float4*>(&W[(size_t)(k0 + brow) * N + n0 + bcol]);
        __syncthreads();

        #pragma unroll
        for (int kk = 0; kk < BK; kk++) {
            float a[4];
            #pragma unroll
            for (int r = 0; r < 4; r++) a[r] = As[ty * 4 + r][kk];
            float4 b4 = *reinterpret_cast<const float4*>(&Bs[kk][tx * 4]);
            float b[4] = {b4.x, b4.y, b4.z, b4.w};
            #pragma unroll
            for (int r = 0; r < 4; r++)
                #pragma unroll
                for (int c = 0; c < 4; c++) acc[r][c] += a[r] * b[c];
        }
        __syncthreads();
    }

    #pragma unroll
    for (int r = 0; r < 4; r++) {
        const int m = m0 + ty * 4 + r;
        #pragma unroll
        for (int c = 0; c < 4; c++) {
            const int n = n0 + tx * 4 + c;
            float v = acc[r][c];
            if (bias) v += bias[n];
            Y[(size_t)m * N + n] = v;
        }
    }
}

// ---------------------------------------------------------------------------
// Batched P@V with causal K truncation. grid.z = batch.
// ---------------------------------------------------------------------------
__global__ __launch_bounds__(NTHREADS) void pv_kernel(
    const float* __restrict__ P, const float* __restrict__ V,
    float* __restrict__ O, int T, int C)
{
    const int b = blockIdx.z;
    const float* Pb = P + (size_t)b * T * T;
    const float* Vb = V + (size_t)b * T * C;
    float* Ob = O + (size_t)b * T * C;

    __shared__ float As[BM][BK];
    __shared__ float Bs[BK][BN];

    const int tid = threadIdx.x;
    const int tx = tid & 15;
    const int ty = tid >> 4;
    const int m0 = blockIdx.y * BM;
    const int n0 = blockIdx.x * BN;

    const int arow = tid >> 2;
    const int acol = (tid & 3) * 4;
    const int brow = tid >> 4;
    const int bcol = (tid & 15) * 4;

    // Row i only attends j <= i; all rows in this tile have i < m0+BM.
    const int Kend = min(T, m0 + BM);

    float acc[4][4];
    #pragma unroll
    for (int r = 0; r < 4; r++)
        #pragma unroll
        for (int c = 0; c < 4; c++) acc[r][c] = 0.0f;

    for (int k0 = 0; k0 < Kend; k0 += BK) {
        *reinterpret_cast<float4*>(&As[arow][acol]) =
            *reinterpret_cast<const float4*>(&Pb[(size_t)(m0 + arow) * T + k0 + acol]);
        *reinterpret_cast<float4*>(&Bs[brow][bcol]) =
            *reinterpret_cast<const float4*>(&Vb[(size_t)(k0 + brow) * C + n0 + bcol]);
        __syncthreads();

        #pragma unroll
        for (int kk = 0; kk < BK; kk++) {
            float a[4];
            #pragma unroll
            for (int r = 0; r < 4; r++) a[r] = As[ty * 4 + r][kk];
            float4 b4 = *reinterpret_cast<const float4*>(&Bs[kk][tx * 4]);
            float b[4] = {b4.x, b4.y, b4.z, b4.w};
            #pragma unroll
            for (int r = 0; r < 4; r++)
                #pragma unroll
                for (int c = 0; c < 4; c++) acc[r][c] += a[r] * b[c];
        }
        __syncthreads();
    }

    #pragma unroll
    for (int r = 0; r < 4; r++) {
        const int m = m0 + ty * 4 + r;
        #pragma unroll
        for (int c = 0; c < 4; c++)
            Ob[(size_t)m * C + n0 + tx * 4 + c] = acc[r][c];
    }
}

// ---------------------------------------------------------------------------
// S[b,i,j] = dot(Q[b,i,:], K[b,j,:]) * rsqrt(C) for j<=i else -inf.
// Tiles entirely above the diagonal just write -inf and exit.
// ---------------------------------------------------------------------------
__global__ __launch_bounds__(NTHREADS) void scores_kernel(
    const float* __restrict__ Q, const float* __restrict__ Kmat,
    float* __restrict__ S, int T, int C)
{
    const int b = blockIdx.z;
    const int i0 = blockIdx.y * BM;
    const int j0 = blockIdx.x * BN;
    const int tid = threadIdx.x;
    const int tx = tid & 15;
    const int ty = tid >> 4;

    float* Sb = S + (size_t)b * T * T;
    const float NEG_INF = __int_as_float(0xff800000);

    if (j0 > i0 + BM - 1) {
        #pragma unroll
        for (int r = 0; r < 4; r++) {
            const int i = i0 + ty * 4 + r;
            #pragma unroll
            for (int c = 0; c < 4; c++)
                Sb[(size_t)i * T + j0 + tx * 4 + c] = NEG_INF;
        }
        return;
    }

    const float* Qb = Q + (size_t)b * T * C;
    const float* Kb = Kmat + (size_t)b * T * C;

    __shared__ float Qs[BM][BK];
    __shared__ float Ks[BN][BK + 1];   // padded: compute reads column-wise

    const int arow = tid >> 2;          // 0..63
    const int acol = (tid & 3) * 4;     // 0,4,8,12

    float acc[4][4];
    #pragma unroll
    for (int r = 0; r < 4; r++)
        #pragma unroll
        for (int c = 0; c < 4; c++) acc[r][c] = 0.0f;

    for (int k0 = 0; k0 < C; k0 += BK) {
        *reinterpret_cast<float4*>(&Qs[arow][acol]) =
            *reinterpret_cast<const float4*>(&Qb[(size_t)(i0 + arow) * C + k0 + acol]);
        float4 kv = *reinterpret_cast<const float4*>(&Kb[(size_t)(j0 + arow) * C + k0 + acol]);
        Ks[arow][acol + 0] = kv.x;
        Ks[arow][acol + 1] = kv.y;
        Ks[arow][acol + 2] = kv.z;
        Ks[arow][acol + 3] = kv.w;
        __syncthreads();

        #pragma unroll
        for (int kk = 0; kk < BK; kk++) {
            float a[4], bb[4];
            #pragma unroll
            for (int r = 0; r < 4; r++) a[r] = Qs[ty * 4 + r][kk];
            #pragma unroll
            for (int c = 0; c < 4; c++) bb[c] = Ks[tx * 4 + c][kk];
            #pragma unroll
            for (int r = 0; r < 4; r++)
                #pragma unroll
                for (int c = 0; c < 4; c++) acc[r][c] += a[r] * bb[c];
        }
        __syncthreads();
    }

    const float scale = rsqrtf((float)C);
    #pragma unroll
    for (int r = 0; r < 4; r++) {
        const int i = i0 + ty * 4 + r;
        #pragma unroll
        for (int c = 0; c < 4; c++) {
            const int j = j0 + tx * 4 + c;
            Sb[(size_t)i * T + j] = (j <= i) ? acc[r][c] * scale : NEG_INF;
        }
    }
}

// ---------------------------------------------------------------------------
// Row softmax over length T (in place). One block per row. -inf -> exact 0.
// ---------------------------------------------------------------------------
__global__ __launch_bounds__(NTHREADS) void softmax_kernel(float* __restrict__ S, int T)
{
    float* p = S + (size_t)blockIdx.x * T;
    __shared__ float red[NTHREADS];
    const int tid = threadIdx.x;

    float m = __int_as_float(0xff800000);
    for (int j = tid; j < T; j += NTHREADS) m = fmaxf(m, p[j]);
    red[tid] = m;
    __syncthreads();
    for (int s = NTHREADS / 2; s > 0; s >>= 1) {
        if (tid < s) red[tid] = fmaxf(red[tid], red[tid + s]);
        __syncthreads();
    }
    m = red[0];
    __syncthreads();

    float sum = 0.0f;
    for (int j = tid; j < T; j += NTHREADS) {
        float e = expf(p[j] - m);
        p[j] = e;
        sum += e;
    }
    red[tid] = sum;
    __syncthreads();
    for (int s = NTHREADS / 2; s > 0; s >>= 1) {
        if (tid < s) red[tid] += red[tid + s];
        __syncthreads();
    }
    const float inv = 1.0f / red[0];
    for (int j = tid; j < T; j += NTHREADS) p[j] *= inv;
}

// ---------------------------------------------------------------------------
// In-place interleaved-pair RoPE (lucidrains-style, theta=10000, full C dim).
// ---------------------------------------------------------------------------
__global__ void rope_kernel(float* __restrict__ X, int Mrows, int T, int C)
{
    const size_t npairs = (size_t)Mrows * (C / 2);
    size_t idx = (size_t)blockIdx.x * blockDim.x + threadIdx.x;
    if (idx >= npairs) return;

    const int halfC = C / 2;
    const int p = (int)(idx % halfC);
    const size_t row = idx / halfC;
    const int t = (int)(row % T);

    const float expo = (float)(2 * p) / (float)C;
    const float inv = powf(10000.0f, -expo);
    const float ang = (float)t * inv;
    float s, c;
    sincosf(ang, &s, &c);

    float* q = X + row * (size_t)C + 2 * p;
    const float e = q[0];
    const float o = q[1];
    q[0] = e * c - o * s;
    q[1] = o * c + e * s;
}

// ---------------------------------------------------------------------------
extern "C" void kernel_launch(void* const* d_in, const int* in_sizes, int n_in,
                              void* d_out, int out_size)
{
    const float* x  = (const float*)d_in[0];
    const float* Wq = (const float*)d_in[1];
    const float* bq = (const float*)d_in[2];
    const float* Wk = (const float*)d_in[3];
    const float* bk = (const float*)d_in[4];
    const float* Wv = (const float*)d_in[5];
    const float* bv = (const float*)d_in[6];
    const float* Wo = (const float*)d_in[7];
    const float* bo = (const float*)d_in[8];

    const int C = in_sizes[2];            // 1024
    const int M = in_sizes[0] / C;        // B*T = 8192
    const int T = kT;                     // 2048 (fixed by the problem)
    const int B = M / T;                  // 4

    float *Q, *K, *V, *O, *S;
    cudaGetSymbolAddress((void**)&Q, g_Q);
    cudaGetSymbolAddress((void**)&K, g_K);
    cudaGetSymbolAddress((void**)&V, g_V);
    cudaGetSymbolAddress((void**)&O, g_O);
    cudaGetSymbolAddress((void**)&S, g_S);

    dim3 gproj(C / BN, M / BM);
    gemm_kernel<<<gproj, NTHREADS>>>(x, Wq, bq, Q, M, C, C, 0);
    gemm_kernel<<<gproj, NTHREADS>>>(x, Wk, bk, K, M, C, C, 0);
    gemm_kernel<<<gproj, NTHREADS>>>(x, Wv, bv, V, M, C, C, 0);

    const size_t npairs = (size_t)M * (C / 2);
    const int rblocks = (int)((npairs + 255) / 256);
    rope_kernel<<<rblocks, 256>>>(Q, M, T, C);
    rope_kernel<<<rblocks, 256>>>(K, M, T, C);

    dim3 gsc(T / BN, T / BM, B);
    scores_kernel<<<gsc, NTHREADS>>>(Q, K, S, T, C);

    softmax_kernel<<<M, NTHREADS>>>(S, T);

    dim3 gpv(C / BN, T / BM, B);
    pv_kernel<<<gpv, NTHREADS>>>(S, V, O, T, C);

    gemm_kernel<<<gproj, NTHREADS>>>(O, Wo, bo, (float*)d_out, M, C, C, 0);

    (void)n_in; (void)out_size;
}

// round 4
// speedup vs baseline: 2.8489x; 2.8489x over previous
#include <cuda_runtime.h>
#include <math.h>
#include <stdint.h>

// ===========================================================================
// Attention_49185965473896 — legacy tensor-core path (mma.sync tf32, sm_100)
//   B=4, T=2048, C=1024 fp32.
// tcgen05 is unavailable (build targets plain sm_100) — use mma.sync.m16n8k8
// tf32 with cp.async multistage pipeline. All GEMMs: D[m,n] = sum_k A[m,k]B[n,k]
// (both operands K-major), weights/V pre-transposed.
// ===========================================================================

#define TT 2048
#define CC 1024
#define NB 4
#define MTOT (NB * TT)

#define BM 128
#define BN 128
#define BK 16
#define PITCH 20                       // floats per smem row (16 data + 4 pad)
#define STAGES 5
#define STAGE_FLOATS ((BM + BN) * PITCH)           // 5120
#define SMEM_BYTES   (STAGES * STAGE_FLOATS * 4)   // 102400

// Scratch (static device arrays; allocation is forbidden)
__device__ float g_Q [(size_t)NB * TT * CC];
__device__ float g_K [(size_t)NB * TT * CC];
__device__ float g_V [(size_t)NB * TT * CC];
__device__ float g_Vt[(size_t)CC * NB * TT];   // [C][B*T]
__device__ float g_O [(size_t)NB * TT * CC];
__device__ float g_S [(size_t)NB * TT * TT];
__device__ float g_Wt[(size_t)4 * CC * CC];

// ---------------------------------------------------------------------------
__device__ __forceinline__ uint32_t smem_u32(const void* p) {
    uint32_t a;
    asm("{ .reg .u64 t; cvta.to.shared.u64 t, %1; cvt.u32.u64 %0, t; }"
        : "=r"(a) : "l"(p));
    return a;
}
__device__ __forceinline__ void cp_async16(uint32_t s, const void* g) {
    asm volatile("cp.async.cg.shared.global [%0], [%1], 16;\n" :: "r"(s), "l"(g));
}
__device__ __forceinline__ uint32_t f2tf(float x) {
    uint32_t r;
    asm("cvt.rna.tf32.f32 %0, %1;" : "=r"(r) : "f"(x));
    return r;
}
__device__ __forceinline__ void mma8(float& c0, float& c1, float& c2, float& c3,
                                     uint32_t a0, uint32_t a1, uint32_t a2, uint32_t a3,
                                     uint32_t b0, uint32_t b1) {
    asm volatile(
        "mma.sync.aligned.m16n8k8.row.col.f32.tf32.tf32.f32 "
        "{%0,%1,%2,%3}, {%4,%5,%6,%7}, {%8,%9}, {%0,%1,%2,%3};"
        : "+f"(c0), "+f"(c1), "+f"(c2), "+f"(c3)
        : "r"(a0), "r"(a1), "r"(a2), "r"(a3), "r"(b0), "r"(b1));
}

// ---------------------------------------------------------------------------
// MODE: 0 = PROJ (+bias)
//       2 = SCORES (scale; skip tiles with n0>m0; no mask writes needed)
//       3 = PV (K truncated at m0+BM)
// ---------------------------------------------------------------------------
template<int MODE>
__global__ __launch_bounds__(256, 1) void mma_kernel(
    const float* __restrict__ A, const float* __restrict__ Bm,
    const float* __restrict__ bias, float* __restrict__ Out,
    int pitchA, int pitchB)
{
    const int m0 = blockIdx.y * BM;
    const int n0 = blockIdx.x * BN;
    const int z  = blockIdx.z;

    if (MODE == 2 && n0 > m0) return;   // strictly-upper tile: nothing to do

    extern __shared__ float smem[];
    const int tid = threadIdx.x;
    const int wid = tid >> 5;
    const int lane = tid & 31;
    const int g = lane >> 2;            // group id 0..7
    const int tg = lane & 3;            // thread-in-group 0..3
    const int wm = wid & 3;             // warp row (4 x 32 rows)
    const int wn = wid >> 2;            // warp col (2 x 64 cols)

    // geometry
    const float* Abase;
    const float* Bbase;
    float* OutB;
    int Klen, outPitch;
    if (MODE == 0) {
        Abase = A + (size_t)m0 * pitchA;
        Bbase = Bm + (size_t)n0 * pitchB;
        OutB = Out; Klen = CC; outPitch = CC;
    } else if (MODE == 2) {
        Abase = A + ((size_t)z * TT + m0) * pitchA;
        Bbase = Bm + ((size_t)z * TT + n0) * pitchB;
        OutB = Out + (size_t)z * TT * TT; Klen = CC; outPitch = TT;
    } else {
        Abase = A + ((size_t)z * TT + m0) * pitchA;
        Bbase = Bm + (size_t)n0 * pitchB + (size_t)z * TT;  // Vt: [C][B*T]
        OutB = Out + (size_t)z * TT * CC; Klen = m0 + BM; outPitch = CC;
    }
    const int KT = Klen / BK;

    float acc[2][8][4];
    #pragma unroll
    for (int mt = 0; mt < 2; mt++)
        #pragma unroll
        for (int nt = 0; nt < 8; nt++)
            #pragma unroll
            for (int c = 0; c < 4; c++) acc[mt][nt][c] = 0.0f;

    // per-thread load geometry: 2 x 16B for A, 2 x 16B for B
    const int r0c = tid >> 2;               // c = tid  -> row
    const int o0c = (tid & 3) * 4;
    const int r1c = (tid + 256) >> 2;       // c = tid+256
    const int o1c = o0c;                    // (tid+256)&3 == tid&3

    auto load_stage = [&](int kt, int slot) {
        float* dA = smem + slot * STAGE_FLOATS;
        float* dB = dA + BM * PITCH;
        const int k0 = kt * BK;
        cp_async16(smem_u32(dA + r0c * PITCH + o0c), Abase + (size_t)r0c * pitchA + k0 + o0c);
        cp_async16(smem_u32(dA + r1c * PITCH + o1c), Abase + (size_t)r1c * pitchA + k0 + o1c);
        cp_async16(smem_u32(dB + r0c * PITCH + o0c), Bbase + (size_t)r0c * pitchB + k0 + o0c);
        cp_async16(smem_u32(dB + r1c * PITCH + o1c), Bbase + (size_t)r1c * pitchB + k0 + o1c);
    };

    // prologue: prefetch STAGES-1 stages
    #pragma unroll
    for (int s = 0; s < STAGES - 1; s++) {
        load_stage(s, s);                       // KT >= 8 always
        asm volatile("cp.async.commit_group;\n" ::);
    }

    for (int kt = 0; kt < KT; kt++) {
        asm volatile("cp.async.wait_group %0;\n" :: "n"(STAGES - 2));
        __syncthreads();

        const int nf = kt + STAGES - 1;
        if (nf < KT) load_stage(nf, nf % STAGES);
        asm volatile("cp.async.commit_group;\n" ::);

        const float* sA = smem + (kt % STAGES) * STAGE_FLOATS;
        const float* sB = sA + BM * PITCH;

        #pragma unroll
        for (int ks = 0; ks < 2; ks++) {
            uint32_t af[2][4], bf[8][2];
            #pragma unroll
            for (int mt = 0; mt < 2; mt++) {
                const float* p = sA + (wm * 32 + mt * 16 + g) * PITCH + ks * 8 + tg;
                af[mt][0] = f2tf(p[0]);
                af[mt][1] = f2tf(p[8 * PITCH]);
                af[mt][2] = f2tf(p[4]);
                af[mt][3] = f2tf(p[8 * PITCH + 4]);
            }
            #pragma unroll
            for (int nt = 0; nt < 8; nt++) {
                const float* p = sB + (wn * 64 + nt * 8 + g) * PITCH + ks * 8 + tg;
                bf[nt][0] = f2tf(p[0]);
                bf[nt][1] = f2tf(p[4]);
            }
            #pragma unroll
            for (int mt = 0; mt < 2; mt++)
                #pragma unroll
                for (int nt = 0; nt < 8; nt++)
                    mma8(acc[mt][nt][0], acc[mt][nt][1], acc[mt][nt][2], acc[mt][nt][3],
                         af[mt][0], af[mt][1], af[mt][2], af[mt][3],
                         bf[nt][0], bf[nt][1]);
        }
    }

    // epilogue: direct register -> gmem (float2 stores)
    const float scale = rsqrtf((float)CC);
    #pragma unroll
    for (int mt = 0; mt < 2; mt++) {
        const int row = m0 + wm * 32 + mt * 16 + g;
        #pragma unroll
        for (int nt = 0; nt < 8; nt++) {
            const int col = n0 + wn * 64 + nt * 8 + 2 * tg;
            float c0 = acc[mt][nt][0], c1 = acc[mt][nt][1];
            float c2 = acc[mt][nt][2], c3 = acc[mt][nt][3];
            if (MODE == 0) {
                const float b0 = __ldg(&bias[col]);
                const float b1 = __ldg(&bias[col + 1]);
                c0 += b0; c1 += b1; c2 += b0; c3 += b1;
            } else if (MODE == 2) {
                c0 *= scale; c1 *= scale; c2 *= scale; c3 *= scale;
            }
            *reinterpret_cast<float2*>(&OutB[(size_t)row * outPitch + col]) =
                make_float2(c0, c1);
            *reinterpret_cast<float2*>(&OutB[(size_t)(row + 8) * outPitch + col]) =
                make_float2(c2, c3);
        }
    }
}

// ---------------------------------------------------------------------------
// Transpose: dst[c][r] = src[r][c], R x Ccols -> Ccols x R (both mult of 32)
// ---------------------------------------------------------------------------
__global__ void transpose_kernel(const float* __restrict__ src, float* __restrict__ dst,
                                 int R, int Ccols)
{
    __shared__ float tile[32][33];
    const int tx = threadIdx.x, ty = threadIdx.y;
    const int x = blockIdx.x * 32 + tx;
    const int y = blockIdx.y * 32 + ty;
    #pragma unroll
    for (int i = 0; i < 32; i += 8)
        tile[ty + i][tx] = src[(size_t)(y + i) * Ccols + x];
    __syncthreads();
    const int x2 = blockIdx.y * 32 + tx;
    const int y2 = blockIdx.x * 32 + ty;
    #pragma unroll
    for (int i = 0; i < 32; i += 8)
        dst[(size_t)(y2 + i) * R + x2] = tile[tx][ty + i];
}

// ---------------------------------------------------------------------------
// Causal softmax over valid prefix [0, i]; zero-fills (i, tile_end).
// Row index within batch: i = blockIdx.x % TT.
// ---------------------------------------------------------------------------
__global__ __launch_bounds__(256) void softmax_kernel(float* __restrict__ S)
{
    float* p = S + (size_t)blockIdx.x * TT;
    const int i = blockIdx.x & (TT - 1);
    const int len = i + 1;
    const int tend = ((i >> 7) + 1) << 7;   // round up to 128
    __shared__ float red[256];
    const int tid = threadIdx.x;

    float m = -3.4e38f;
    for (int j = tid; j < len; j += 256) m = fmaxf(m, p[j]);
    red[tid] = m;
    __syncthreads();
    for (int s = 128; s > 0; s >>= 1) {
        if (tid < s) red[tid] = fmaxf(red[tid], red[tid + s]);
        __syncthreads();
    }
    m = red[0];
    __syncthreads();

    float sum = 0.0f;
    for (int j = tid; j < tend; j += 256) {
        if (j < len) {
            float e = expf(p[j] - m);
            p[j] = e;
            sum += e;
        } else {
            p[j] = 0.0f;
        }
    }
    red[tid] = sum;
    __syncthreads();
    for (int s = 128; s > 0; s >>= 1) {
        if (tid < s) red[tid] += red[tid + s];
        __syncthreads();
    }
    const float inv = 1.0f / red[0];
    for (int j = tid; j < len; j += 256) p[j] *= inv;
}

// ---------------------------------------------------------------------------
// In-place interleaved-pair RoPE (theta=10000, full C dim).
// ---------------------------------------------------------------------------
__global__ void rope_kernel(float* __restrict__ X)
{
    const size_t idx = (size_t)blockIdx.x * blockDim.x + threadIdx.x;
    const int halfC = CC / 2;
    const int p = (int)(idx % halfC);
    const size_t row = idx / halfC;
    const int t = (int)(row & (TT - 1));

    const float expo = (float)(2 * p) / (float)CC;
    const float inv = powf(10000.0f, -expo);
    const float ang = (float)t * inv;
    float s, c;
    sincosf(ang, &s, &c);

    float* q = X + row * (size_t)CC + 2 * p;
    const float e = q[0];
    const float o = q[1];
    q[0] = e * c - o * s;
    q[1] = o * c + e * s;
}

// ---------------------------------------------------------------------------
extern "C" void kernel_launch(void* const* d_in, const int* in_sizes, int n_in,
                              void* d_out, int out_size)
{
    const float* x  = (const float*)d_in[0];
    const float* Wq = (const float*)d_in[1];
    const float* bq = (const float*)d_in[2];
    const float* Wk = (const float*)d_in[3];
    const float* bk = (const float*)d_in[4];
    const float* Wv = (const float*)d_in[5];
    const float* bv = (const float*)d_in[6];
    const float* Wo = (const float*)d_in[7];
    const float* bo = (const float*)d_in[8];

    float *Q, *K, *V, *Vt, *O, *S, *Wt;
    cudaGetSymbolAddress((void**)&Q,  g_Q);
    cudaGetSymbolAddress((void**)&K,  g_K);
    cudaGetSymbolAddress((void**)&V,  g_V);
    cudaGetSymbolAddress((void**)&Vt, g_Vt);
    cudaGetSymbolAddress((void**)&O,  g_O);
    cudaGetSymbolAddress((void**)&S,  g_S);
    cudaGetSymbolAddress((void**)&Wt, g_Wt);

    cudaFuncSetAttribute(mma_kernel<0>, cudaFuncAttributeMaxDynamicSharedMemorySize, SMEM_BYTES);
    cudaFuncSetAttribute(mma_kernel<2>, cudaFuncAttributeMaxDynamicSharedMemorySize, SMEM_BYTES);
    cudaFuncSetAttribute(mma_kernel<3>, cudaFuncAttributeMaxDynamicSharedMemorySize, SMEM_BYTES);

    // weight transposes (Wt[n][k] = W[k][n])
    dim3 tb(32, 8);
    dim3 tgw(CC / 32, CC / 32);
    transpose_kernel<<<tgw, tb>>>(Wq, Wt + 0 * (size_t)CC * CC, CC, CC);
    transpose_kernel<<<tgw, tb>>>(Wk, Wt + 1 * (size_t)CC * CC, CC, CC);
    transpose_kernel<<<tgw, tb>>>(Wv, Wt + 2 * (size_t)CC * CC, CC, CC);
    transpose_kernel<<<tgw, tb>>>(Wo, Wt + 3 * (size_t)CC * CC, CC, CC);

    // projections
    dim3 gproj(CC / BN, MTOT / BM, 1);
    mma_kernel<0><<<gproj, 256, SMEM_BYTES>>>(x, Wt + 0 * (size_t)CC * CC, bq, Q, CC, CC);
    mma_kernel<0><<<gproj, 256, SMEM_BYTES>>>(x, Wt + 1 * (size_t)CC * CC, bk, K, CC, CC);
    mma_kernel<0><<<gproj, 256, SMEM_BYTES>>>(x, Wt + 2 * (size_t)CC * CC, bv, V, CC, CC);

    // RoPE on Q, K
    const int rblocks = (int)(((size_t)MTOT * (CC / 2)) / 256);
    rope_kernel<<<rblocks, 256>>>(Q);
    rope_kernel<<<rblocks, 256>>>(K);

    // V transpose: [B*T][C] -> [C][B*T]
    dim3 tgv(CC / 32, MTOT / 32);
    transpose_kernel<<<tgv, tb>>>(V, Vt, MTOT, CC);

    // scores: S = QK^T * rsqrt(C), lower/diag tiles only
    dim3 gsc(TT / BN, TT / BM, NB);
    mma_kernel<2><<<gsc, 256, SMEM_BYTES>>>(Q, K, nullptr, S, CC, CC);

    softmax_kernel<<<MTOT, 256>>>(S);

    // O = P @ V
    dim3 gpv(CC / BN, TT / BM, NB);
    mma_kernel<3><<<gpv, 256, SMEM_BYTES>>>(S, Vt, nullptr, O, TT, MTOT);

    // out = O @ Wo + bo
    mma_kernel<0><<<gproj, 256, SMEM_BYTES>>>(O, Wt + 3 * (size_t)CC * CC, bo, (float*)d_out, CC, CC);

    (void)n_in; (void)out_size; (void)in_sizes;
}